// round 1
// baseline (speedup 1.0000x reference)
#include <cuda_runtime.h>
#include <math.h>

#define B_   16
#define L_   18
#define SQ_  256
#define H_   2560
#define R_   256
#define D_   2048
#define C_   32
#define TOPK_ 16

// Scratch (no allocations allowed -> device globals)
__device__ float g_qvec[B_ * L_ * R_];          // 1.18 MB
__device__ float g_sims[B_ * D_ * L_];          // 2.36 MB  [b][d][l]

// ---------------------------------------------------------------------------
// Kernel A: per-(b,l) GEMM  C[s,r] = sum_h q_hs[b,l,s,h] * w_q[l,r,h]
// then max over s, written to g_qvec[b,l,r]. Block = 256 thr, tile 128x128x16,
// 8x8 register micro-tile, double-buffered smem, m-loop (2 tiles) inside block.
// ---------------------------------------------------------------------------
__global__ void __launch_bounds__(256, 2)
qproj_kernel(const float* __restrict__ q_hs, const float* __restrict__ w_q) {
    const int nt = blockIdx.x;   // r-tile: 0..1
    const int l  = blockIdx.y;
    const int b  = blockIdx.z;

    const float* Abase = q_hs + ((size_t)(b * L_ + l)) * SQ_ * H_;
    const float* Wbase = w_q + (size_t)l * R_ * H_ + (size_t)nt * 128 * H_;

    __shared__ float As[2][16][132];   // [buf][k][m], padded
    __shared__ float Bs[2][16][132];   // [buf][k][n]
    __shared__ float red[16][128];

    const int tid = threadIdx.x;
    const int tx  = tid & 15;     // n group
    const int ty  = tid >> 4;     // m group

    // load mapping: 512 float4 per tile, 2 per thread
    const int lr0 = tid >> 2;     // rows 0..63
    const int lc  = tid & 3;      // col-quad 0..3
    const int lr1 = lr0 + 64;

    float cmax[8];
#pragma unroll
    for (int j = 0; j < 8; j++) cmax[j] = -INFINITY;

    float4 ra0, ra1, rb0, rb1;

#define LOAD_TILE(Aptr, K0)                                                    \
    do {                                                                       \
        ra0 = *(const float4*)((Aptr) + (size_t)lr0 * H_ + (K0) + lc * 4);     \
        ra1 = *(const float4*)((Aptr) + (size_t)lr1 * H_ + (K0) + lc * 4);     \
        rb0 = *(const float4*)(Wbase + (size_t)lr0 * H_ + (K0) + lc * 4);      \
        rb1 = *(const float4*)(Wbase + (size_t)lr1 * H_ + (K0) + lc * 4);      \
    } while (0)

#define STORE_TILE(BUF)                                                        \
    do {                                                                       \
        As[BUF][lc * 4 + 0][lr0] = ra0.x; As[BUF][lc * 4 + 1][lr0] = ra0.y;    \
        As[BUF][lc * 4 + 2][lr0] = ra0.z; As[BUF][lc * 4 + 3][lr0] = ra0.w;    \
        As[BUF][lc * 4 + 0][lr1] = ra1.x; As[BUF][lc * 4 + 1][lr1] = ra1.y;    \
        As[BUF][lc * 4 + 2][lr1] = ra1.z; As[BUF][lc * 4 + 3][lr1] = ra1.w;    \
        Bs[BUF][lc * 4 + 0][lr0] = rb0.x; Bs[BUF][lc * 4 + 1][lr0] = rb0.y;    \
        Bs[BUF][lc * 4 + 2][lr0] = rb0.z; Bs[BUF][lc * 4 + 3][lr0] = rb0.w;    \
        Bs[BUF][lc * 4 + 0][lr1] = rb1.x; Bs[BUF][lc * 4 + 1][lr1] = rb1.y;    \
        Bs[BUF][lc * 4 + 2][lr1] = rb1.z; Bs[BUF][lc * 4 + 3][lr1] = rb1.w;    \
    } while (0)

    for (int mt = 0; mt < 2; mt++) {
        const float* A = Abase + (size_t)mt * 128 * H_;

        float acc[8][8];
#pragma unroll
        for (int i = 0; i < 8; i++)
#pragma unroll
            for (int j = 0; j < 8; j++) acc[i][j] = 0.0f;

        LOAD_TILE(A, 0);
        STORE_TILE(0);
        __syncthreads();

        const int NST = H_ / 16;   // 160
        for (int s = 0; s < NST; s++) {
            const int buf = s & 1;
            if (s + 1 < NST) LOAD_TILE(A, (s + 1) * 16);

#pragma unroll
            for (int k = 0; k < 16; k++) {
                float4 a0 = *(const float4*)&As[buf][k][ty * 8];
                float4 a1 = *(const float4*)&As[buf][k][ty * 8 + 4];
                float4 b0 = *(const float4*)&Bs[buf][k][tx * 8];
                float4 b1 = *(const float4*)&Bs[buf][k][tx * 8 + 4];
                float av[8] = {a0.x, a0.y, a0.z, a0.w, a1.x, a1.y, a1.z, a1.w};
                float bv[8] = {b0.x, b0.y, b0.z, b0.w, b1.x, b1.y, b1.z, b1.w};
#pragma unroll
                for (int i = 0; i < 8; i++)
#pragma unroll
                    for (int j = 0; j < 8; j++)
                        acc[i][j] = fmaf(av[i], bv[j], acc[i][j]);
            }

            if (s + 1 < NST) {
                STORE_TILE(buf ^ 1);
                __syncthreads();
            }
        }

        // fold this m-tile into the per-column running max
#pragma unroll
        for (int i = 0; i < 8; i++)
#pragma unroll
            for (int j = 0; j < 8; j++) cmax[j] = fmaxf(cmax[j], acc[i][j]);
    }

    // reduce max across the 16 m-thread-groups
#pragma unroll
    for (int j = 0; j < 8; j++) red[ty][tx * 8 + j] = cmax[j];
    __syncthreads();
    if (tid < 128) {
        float m = red[0][tid];
#pragma unroll
        for (int i = 1; i < 16; i++) m = fmaxf(m, red[i][tid]);
        g_qvec[((size_t)(b * L_ + l)) * R_ + nt * 128 + tid] = m;
    }
#undef LOAD_TILE
#undef STORE_TILE
}

// ---------------------------------------------------------------------------
// Kernel A2: L2-normalize each of the 288 rows of g_qvec (len 256) in place.
// ---------------------------------------------------------------------------
__global__ void qnorm_kernel() {
    const int row = blockIdx.x;
    const int tid = threadIdx.x;   // 256
    float v = g_qvec[(size_t)row * R_ + tid];
    __shared__ float sm[256];
    sm[tid] = v * v;
    __syncthreads();
    for (int s = 128; s > 0; s >>= 1) {
        if (tid < s) sm[tid] += sm[tid + s];
        __syncthreads();
    }
    float inv = 1.0f / fmaxf(sqrtf(sm[0]), 1e-12f);
    g_qvec[(size_t)row * R_ + tid] = v * inv;
}

// ---------------------------------------------------------------------------
// Kernel B: per-(d,l) block. Normalize each of the 32 chunk keys on the fly,
// dot with all 16 normalized query vectors, max over chunks -> g_sims[b,d,l].
// Warp-per-chunk, 4 chunks per warp.
// ---------------------------------------------------------------------------
__global__ void __launch_bounds__(256)
docsim_kernel(const float* __restrict__ doc_keys) {
    const int d = blockIdx.x;
    const int l = blockIdx.y;
    const int tid = threadIdx.x;

    __shared__ float4 qs[B_ * 64];   // [b][r/4], 16 KB
    for (int i = tid; i < B_ * 64; i += 256) {
        int b = i >> 6, j = i & 63;
        qs[i] = *(const float4*)&g_qvec[((size_t)(b * L_ + l)) * R_ + j * 4];
    }
    __syncthreads();

    const int w = tid >> 5, lane = tid & 31;
    float bmax[16];
#pragma unroll
    for (int b = 0; b < 16; b++) bmax[b] = -INFINITY;

    const float* kb = doc_keys + ((size_t)(d * L_ + l)) * C_ * R_;

    for (int ci = 0; ci < 4; ci++) {
        const int c = w * 4 + ci;
        const float4* kp = (const float4*)(kb + (size_t)c * R_);
        float4 k0 = kp[lane];
        float4 k1 = kp[lane + 32];

        float n2 = k0.x * k0.x + k0.y * k0.y + k0.z * k0.z + k0.w * k0.w +
                   k1.x * k1.x + k1.y * k1.y + k1.z * k1.z + k1.w * k1.w;
#pragma unroll
        for (int off = 16; off > 0; off >>= 1)
            n2 += __shfl_xor_sync(0xffffffffu, n2, off);
        const float inv = 1.0f / fmaxf(sqrtf(n2), 1e-12f);

#pragma unroll
        for (int b = 0; b < 16; b++) {
            float4 q0 = qs[b * 64 + lane];
            float4 q1 = qs[b * 64 + 32 + lane];
            float p = k0.x * q0.x + k0.y * q0.y + k0.z * q0.z + k0.w * q0.w +
                      k1.x * q1.x + k1.y * q1.y + k1.z * q1.z + k1.w * q1.w;
#pragma unroll
            for (int off = 16; off > 0; off >>= 1)
                p += __shfl_xor_sync(0xffffffffu, p, off);
            bmax[b] = fmaxf(bmax[b], p * inv);
        }
    }

    __shared__ float red[8][16];
    if (lane == 0) {
#pragma unroll
        for (int b = 0; b < 16; b++) red[w][b] = bmax[b];
    }
    __syncthreads();
    if (tid < 16) {
        float m = red[0][tid];
#pragma unroll
        for (int i = 1; i < 8; i++) m = fmaxf(m, red[i][tid]);
        g_sims[((size_t)(tid * D_ + d)) * L_ + l] = m;
    }
}

// ---------------------------------------------------------------------------
// Kernel C: per-b block: scores[d] = mean_l sims[b,d,l]; exact top-16
// (descending, ties -> lower index first), write scores then indices (as f32).
// ---------------------------------------------------------------------------
__global__ void topk_kernel(float* __restrict__ out, int out_size) {
    const int b = blockIdx.x;
    const int tid = threadIdx.x;   // 256
    __shared__ float sv[D_];
    for (int i = tid; i < D_; i += 256) {
        const float* p = &g_sims[((size_t)(b * D_ + i)) * L_];
        float ssum = 0.0f;
#pragma unroll
        for (int l = 0; l < L_; l++) ssum += p[l];
        sv[i] = ssum / (float)L_;
    }
    __syncthreads();

    __shared__ float rv[256];
    __shared__ int ri[256];
    for (int k = 0; k < TOPK_; k++) {
        float best = -INFINITY;
        int bi = 0x7fffffff;
        for (int i = tid; i < D_; i += 256) {
            float v = sv[i];
            if (v > best || (v == best && i < bi)) { best = v; bi = i; }
        }
        rv[tid] = best; ri[tid] = bi;
        __syncthreads();
        for (int s = 128; s > 0; s >>= 1) {
            if (tid < s) {
                float v2 = rv[tid + s]; int i2 = ri[tid + s];
                if (v2 > rv[tid] || (v2 == rv[tid] && i2 < ri[tid])) {
                    rv[tid] = v2; ri[tid] = i2;
                }
            }
            __syncthreads();
        }
        if (tid == 0) {
            out[b * TOPK_ + k] = rv[0];
            if (out_size >= 2 * B_ * TOPK_)
                out[B_ * TOPK_ + b * TOPK_ + k] = (float)ri[0];
            sv[ri[0]] = -INFINITY;
        }
        __syncthreads();
    }
}

// ---------------------------------------------------------------------------
extern "C" void kernel_launch(void* const* d_in, const int* in_sizes, int n_in,
                              void* d_out, int out_size) {
    const float* q_hs     = (const float*)d_in[0];
    const float* w_q      = (const float*)d_in[1];
    const float* doc_keys = (const float*)d_in[2];
    // d_in[3] = top_k scalar (constant 16, baked in)
    (void)in_sizes; (void)n_in;

    dim3 gA(2, L_, B_);
    qproj_kernel<<<gA, 256>>>(q_hs, w_q);

    qnorm_kernel<<<B_ * L_, 256>>>();

    dim3 gB(D_, L_);
    docsim_kernel<<<gB, 256>>>(doc_keys);

    topk_kernel<<<B_, 256>>>((float*)d_out, out_size);
}